// round 1
// baseline (speedup 1.0000x reference)
#include <cuda_runtime.h>
#include <math.h>

#define N_PTS 8192
#define M_PTS 2048
#define K_LAST 10
#define VARS 3

// exact GELU (matches jax.nn.gelu approximate=False)
__device__ __forceinline__ float gelu(float x) {
    return 0.5f * x * (1.0f + erff(x * 0.70710678118654752f));
}

// scratch (static device globals: no allocation allowed)
__device__ float g_f0[VARS * N_PTS * 32];
__device__ float g_acc[VARS * N_PTS * 32];

// ---------------------------------------------------------------------------
// Projection MLP: per (var, point): x[8] -> gelu(x@W0+b0)[64] -> @W1+b1 [32]
// one warp per (var,point); hidden staged in shared per warp.
// ---------------------------------------------------------------------------
__global__ void proj_kernel(const float* __restrict__ inp,
                            const float* __restrict__ W0, const float* __restrict__ b0,
                            const float* __restrict__ W1, const float* __restrict__ b1,
                            float* __restrict__ f0) {
    __shared__ float hs[4][64];
    int warp = threadIdx.x >> 5, lane = threadIdx.x & 31;
    int pv = blockIdx.x * 4 + warp;           // pv = v*N_PTS + n
    if (pv >= VARS * N_PTS) return;
    int v = pv / N_PTS, n = pv - v * N_PTS;
    const float* x = inp + n * (VARS * 8) + v * 8;
    float xr[8];
#pragma unroll
    for (int i = 0; i < 8; i++) xr[i] = x[i];
    float a0 = b0[lane], a1 = b0[lane + 32];
#pragma unroll
    for (int i = 0; i < 8; i++) {
        a0 = fmaf(xr[i], W0[i * 64 + lane], a0);
        a1 = fmaf(xr[i], W0[i * 64 + lane + 32], a1);
    }
    hs[warp][lane]      = gelu(a0);
    hs[warp][lane + 32] = gelu(a1);
    __syncwarp();
    float acc = b1[lane];
#pragma unroll
    for (int h = 0; h < 64; h++) acc = fmaf(hs[warp][h], W1[h * 32 + lane], acc);
    f0[(size_t)pv * 32 + lane] = acc;
}

// ---------------------------------------------------------------------------
// Edge MLP 36 -> 80 (gelu) -> 80 (gelu) -> 32, one thread per edge.
// Weights in shared (W1 transposed for vectorized loads). h1 per-thread in
// shared, stride 84 floats (21 float4s, odd -> conflict-free LDS.128).
// MODE 0: radius graph, atomic segment-sum into acc buffer.
// MODE 1: knn graph, atomic mean (x0.1) into final output.
// ---------------------------------------------------------------------------
template <int MODE>
__global__ void __launch_bounds__(128)
edge_kernel(const float* __restrict__ Wa, const float* __restrict__ ba,
            const float* __restrict__ Wb, const float* __restrict__ bb,
            const float* __restrict__ Wc, const float* __restrict__ bc,
            const float* __restrict__ grid_in, const float* __restrict__ grid_out,
            const float* __restrict__ fsrc,
            const int* __restrict__ idxA, const int* __restrict__ idxB,
            float* __restrict__ outbuf, int E) {
    extern __shared__ float sm[];
    float* W0s  = sm;                  // 36*80 = 2880
    float* b0s  = W0s + 36 * 80;       // 80
    float* W1Ts = b0s + 80;            // 80*80 = 6400 (transposed: [j][i])
    float* b1s  = W1Ts + 80 * 80;      // 80
    float* W2s  = b1s + 80;            // 80*32 = 2560 ([j][o])
    float* b2s  = W2s + 80 * 32;       // 32
    float* h1s  = b2s + 32;            // 128 * 84

    int tid = threadIdx.x;
    for (int i = tid; i < 36 * 80; i += 128) W0s[i] = Wa[i];
    for (int i = tid; i < 80 * 80; i += 128) W1Ts[(i % 80) * 80 + (i / 80)] = Wb[i];
    for (int i = tid; i < 80 * 32; i += 128) W2s[i] = Wc[i];
    if (tid < 80) { b0s[tid] = ba[tid]; b1s[tid] = bb[tid]; }
    if (tid < 32) b2s[tid] = bc[tid];
    __syncthreads();

    int e = blockIdx.x * 128 + tid;
    if (e >= E) return;
    int v = blockIdx.y;

    // gather input: [pos_nbr(2), pos_self(2), f[nbr](32)]
    float in[36];
    int segd;
    int jn = idxA[e];
    if (MODE == 0) {
        segd = idxB[e];
        in[0] = grid_in[2 * jn];   in[1] = grid_in[2 * jn + 1];
        in[2] = grid_in[2 * segd]; in[3] = grid_in[2 * segd + 1];
    } else {
        segd = e / K_LAST;
        in[0] = grid_in[2 * jn];    in[1] = grid_in[2 * jn + 1];
        in[2] = grid_out[2 * segd]; in[3] = grid_out[2 * segd + 1];
    }
    const float4* fpv = (const float4*)(fsrc + ((size_t)v * N_PTS + jn) * 32);
#pragma unroll
    for (int q = 0; q < 8; q++) {
        float4 t = fpv[q];
        in[4 + 4 * q] = t.x; in[5 + 4 * q] = t.y;
        in[6 + 4 * q] = t.z; in[7 + 4 * q] = t.w;
    }

    float4* myh = (float4*)(h1s + tid * 84);   // 21 float4s, odd stride

    // ---- layer 1: 36 -> 80, 10 tiles of 8 outputs ----
#pragma unroll 1
    for (int jt = 0; jt < 10; jt++) {
        float acc[8];
#pragma unroll
        for (int k = 0; k < 8; k++) acc[k] = b0s[jt * 8 + k];
#pragma unroll
        for (int i = 0; i < 36; i++) {
            const float4* w = (const float4*)(W0s + i * 80 + jt * 8);
            float4 w0 = w[0], w1 = w[1];
            float xi = in[i];
            acc[0] = fmaf(xi, w0.x, acc[0]); acc[1] = fmaf(xi, w0.y, acc[1]);
            acc[2] = fmaf(xi, w0.z, acc[2]); acc[3] = fmaf(xi, w0.w, acc[3]);
            acc[4] = fmaf(xi, w1.x, acc[4]); acc[5] = fmaf(xi, w1.y, acc[5]);
            acc[6] = fmaf(xi, w1.z, acc[6]); acc[7] = fmaf(xi, w1.w, acc[7]);
        }
        myh[jt * 2]     = make_float4(gelu(acc[0]), gelu(acc[1]), gelu(acc[2]), gelu(acc[3]));
        myh[jt * 2 + 1] = make_float4(gelu(acc[4]), gelu(acc[5]), gelu(acc[6]), gelu(acc[7]));
    }

    // ---- layers 2+3 fused: 80 -> 80 (gelu) streamed into 80 -> 32 ----
    float out[32];
#pragma unroll
    for (int o = 0; o < 32; o++) out[o] = b2s[o];

#pragma unroll 1
    for (int jt = 0; jt < 20; jt++) {          // 4 h2 outputs per tile
        float acc[4];
#pragma unroll
        for (int k = 0; k < 4; k++) acc[k] = b1s[jt * 4 + k];
#pragma unroll
        for (int it = 0; it < 20; it++) {      // 4 h1 inputs per step
            float4 h = myh[it];
#pragma unroll
            for (int k = 0; k < 4; k++) {
                float4 w = *(const float4*)(W1Ts + (jt * 4 + k) * 80 + it * 4);
                acc[k] = fmaf(h.x, w.x, acc[k]);
                acc[k] = fmaf(h.y, w.y, acc[k]);
                acc[k] = fmaf(h.z, w.z, acc[k]);
                acc[k] = fmaf(h.w, w.w, acc[k]);
            }
        }
#pragma unroll
        for (int k = 0; k < 4; k++) {
            float g = gelu(acc[k]);
            const float4* w2 = (const float4*)(W2s + (jt * 4 + k) * 32);
#pragma unroll
            for (int ot = 0; ot < 8; ot++) {
                float4 w = w2[ot];
                out[4 * ot + 0] = fmaf(g, w.x, out[4 * ot + 0]);
                out[4 * ot + 1] = fmaf(g, w.y, out[4 * ot + 1]);
                out[4 * ot + 2] = fmaf(g, w.z, out[4 * ot + 2]);
                out[4 * ot + 3] = fmaf(g, w.w, out[4 * ot + 3]);
            }
        }
    }

    // ---- scatter ----
    float* dst; float scale;
    if (MODE == 0) { dst = outbuf + ((size_t)v * N_PTS + segd) * 32; scale = 1.0f; }
    else           { dst = outbuf + (size_t)segd * (VARS * 32) + v * 32; scale = 0.1f; }
#pragma unroll
    for (int o = 0; o < 32; o++) atomicAdd(dst + o, out[o] * scale);
}

// f1 = segment_sum * inv_count + f0   (in place into f0)
__global__ void f1_kernel(float* __restrict__ f0, const float* __restrict__ acc,
                          const int* __restrict__ counts) {
    int idx = blockIdx.x * 256 + threadIdx.x;
    if (idx >= VARS * N_PTS * 32) return;
    int n = (idx >> 5) % N_PTS;
    int c = counts[n];
    float inv = 1.0f / (float)(c > 1 ? c : 1);
    f0[idx] = fmaf(acc[idx], inv, f0[idx]);
}

extern "C" void kernel_launch(void* const* d_in, const int* in_sizes, int n_in,
                              void* d_out, int out_size) {
    const float* inp   = (const float*)d_in[0];
    const float* gin   = (const float*)d_in[1];
    const float* gout  = (const float*)d_in[2];
    const float* pW0   = (const float*)d_in[3];
    const float* pb0   = (const float*)d_in[4];
    const float* pW1   = (const float*)d_in[5];
    const float* pb1   = (const float*)d_in[6];
    const float* i0W0  = (const float*)d_in[7];
    const float* i0b0  = (const float*)d_in[8];
    const float* i0W1  = (const float*)d_in[9];
    const float* i0b1  = (const float*)d_in[10];
    const float* i0W2  = (const float*)d_in[11];
    const float* i0b2  = (const float*)d_in[12];
    const float* i1W0  = (const float*)d_in[13];
    const float* i1b0  = (const float*)d_in[14];
    const float* i1W1  = (const float*)d_in[15];
    const float* i1b1  = (const float*)d_in[16];
    const float* i1W2  = (const float*)d_in[17];
    const float* i1b2  = (const float*)d_in[18];
    const int* nbr_index = (const int*)d_in[19];
    const int* nbr_seg   = (const int*)d_in[20];
    const int* nbr_counts= (const int*)d_in[21];
    const int* nbr_last  = (const int*)d_in[22];
    int E = in_sizes[19];

    float *f0, *acc;
    cudaGetSymbolAddress((void**)&f0,  g_f0);
    cudaGetSymbolAddress((void**)&acc, g_acc);

    cudaMemsetAsync(acc, 0, sizeof(float) * VARS * N_PTS * 32);
    cudaMemsetAsync(d_out, 0, sizeof(float) * (size_t)out_size);

    proj_kernel<<<(VARS * N_PTS + 3) / 4, 128>>>(inp, pW0, pb0, pW1, pb1, f0);

    const int SMEM = (36*80 + 80 + 80*80 + 80 + 80*32 + 32 + 128*84) * (int)sizeof(float);
    cudaFuncSetAttribute(edge_kernel<0>, cudaFuncAttributeMaxDynamicSharedMemorySize, SMEM);
    cudaFuncSetAttribute(edge_kernel<1>, cudaFuncAttributeMaxDynamicSharedMemorySize, SMEM);

    dim3 g1((unsigned)((E + 127) / 128), VARS);
    edge_kernel<0><<<g1, 128, SMEM>>>(i0W0, i0b0, i0W1, i0b1, i0W2, i0b2,
                                      gin, nullptr, f0, nbr_index, nbr_seg, acc, E);

    f1_kernel<<<(VARS * N_PTS * 32 + 255) / 256, 256>>>(f0, acc, nbr_counts);

    int E2 = M_PTS * K_LAST;
    dim3 g2((unsigned)((E2 + 127) / 128), VARS);
    edge_kernel<1><<<g2, 128, SMEM>>>(i1W0, i1b0, i1W1, i1b1, i1W2, i1b2,
                                      gin, gout, f0, nbr_last, nullptr, (float*)d_out, E2);
}